// round 1
// baseline (speedup 1.0000x reference)
#include <cuda_runtime.h>
#include <cuda_bf16.h>

// GATConv heads=1: out[dst] = bias + sum_{e: dst} softmax_dst(lrelu(as[src]+ad[dst])) * h[src]
// with self loops appended. h = x @ W.

#define IN_DIM   128
#define OUT_DIM  64
#define N_MAX    100000
#define E_MAX    1600000
#define NEG_SLOPE 0.2f

// ---------------- device scratch (no allocations allowed) ----------------
__device__ __align__(16) float g_h[(size_t)N_MAX * OUT_DIM];   // 25.6 MB
__device__ float g_as[N_MAX];
__device__ float g_ad[N_MAX];
__device__ float g_s[N_MAX];
__device__ float g_ex[E_MAX + N_MAX];

// ---------------- K0: init out = bias, s = 0 ----------------
__global__ void k_init(float* __restrict__ out, const float* __restrict__ bias, int N) {
    int i = blockIdx.x * blockDim.x + threadIdx.x;
    if (i < N * OUT_DIM) out[i] = bias[i & (OUT_DIM - 1)];
    if (i < N) g_s[i] = 0.0f;
}

// ---------------- K1: h = x @ W  (fp32, f32x2-packed FMA) ----------------
// Tile: 64 rows x 64 cols, K=128. W full tile in smem (32KB), x tile padded stride 129.
#define TR 64
#define GEMM_SMEM (IN_DIM * OUT_DIM * 4 + TR * 129 * 4)  // 32768 + 33024 = 65792

__global__ __launch_bounds__(256) void k_gemm(const float* __restrict__ x,
                                              const float* __restrict__ W, int N) {
    extern __shared__ float smem[];
    float* Ws = smem;                    // [128][64], 16B aligned
    float* Xs = smem + IN_DIM * OUT_DIM; // [64][129]

    int tid = threadIdx.x;
    int rowBase = blockIdx.x * TR;

    // load W: 8192 floats = 2048 float4
    for (int i = tid; i < (IN_DIM * OUT_DIM) / 4; i += 256)
        ((float4*)Ws)[i] = ((const float4*)W)[i];

    // load x tile: 64 rows x 128, as float4, scatter to padded smem
    for (int i = tid; i < (TR * IN_DIM) / 4; i += 256) {
        int r  = i >> 5;        // 0..63
        int kq = i & 31;        // float4 index within row
        int row = rowBase + r;
        float4 v = (row < N) ? ((const float4*)x)[(size_t)row * 32 + kq]
                             : make_float4(0.f, 0.f, 0.f, 0.f);
        float* p = &Xs[r * 129 + kq * 4];
        p[0] = v.x; p[1] = v.y; p[2] = v.z; p[3] = v.w;
    }
    __syncthreads();

    int w    = tid >> 5;
    int lane = tid & 31;
    int rl   = ((w & 1) << 5) + lane;   // local row 0..63
    int cb   = (w >> 1) << 4;           // col base: 0,16,32,48

    unsigned long long acc[8];          // 8 x f32x2 = 16 cols
#pragma unroll
    for (int j = 0; j < 8; j++) acc[j] = 0ULL;

    const ulonglong2* Ws2 = (const ulonglong2*)Ws;  // 16B packs: 4 cols each

#pragma unroll 8
    for (int k = 0; k < IN_DIM; k++) {
        float xv = Xs[rl * 129 + k];
        unsigned long long xp;
        asm("mov.b64 %0, {%1, %1};" : "=l"(xp) : "f"(xv));
        int base = k * 16 + (cb >> 2);
#pragma unroll
        for (int j = 0; j < 4; j++) {
            ulonglong2 ww = Ws2[base + j];
            asm("fma.rn.f32x2 %0, %1, %2, %0;" : "+l"(acc[2 * j])     : "l"(xp), "l"(ww.x));
            asm("fma.rn.f32x2 %0, %1, %2, %0;" : "+l"(acc[2 * j + 1]) : "l"(xp), "l"(ww.y));
        }
    }

    int row = rowBase + rl;
    if (row < N) {
        float tmp[16];
#pragma unroll
        for (int j = 0; j < 8; j++) {
            float lo, hi;
            asm("mov.b64 {%0, %1}, %2;" : "=f"(lo), "=f"(hi) : "l"(acc[j]));
            tmp[2 * j] = lo; tmp[2 * j + 1] = hi;
        }
        float4* hp = (float4*)(g_h + (size_t)row * OUT_DIM + cb);
#pragma unroll
        for (int j = 0; j < 4; j++)
            hp[j] = make_float4(tmp[4 * j], tmp[4 * j + 1], tmp[4 * j + 2], tmp[4 * j + 3]);
    }
}

// ---------------- K1b: per-node attention logits (warp per node) ----------------
__global__ __launch_bounds__(256) void k_alpha(const float* __restrict__ a_src,
                                               const float* __restrict__ a_dst, int N) {
    int gwarp = (blockIdx.x * blockDim.x + threadIdx.x) >> 5;
    int lane  = threadIdx.x & 31;
    if (gwarp >= N) return;
    const float* hr = g_h + (size_t)gwarp * OUT_DIM;
    float v0 = hr[lane], v1 = hr[lane + 32];
    float ps = v0 * a_src[lane] + v1 * a_src[lane + 32];
    float pd = v0 * a_dst[lane] + v1 * a_dst[lane + 32];
#pragma unroll
    for (int o = 16; o; o >>= 1) {
        ps += __shfl_down_sync(0xFFFFFFFFu, ps, o);
        pd += __shfl_down_sync(0xFFFFFFFFu, pd, o);
    }
    if (lane == 0) { g_as[gwarp] = ps; g_ad[gwarp] = pd; }
}

// ---------------- K2: per-edge exp + denominator ----------------
// Edge ids [0,E) are real edges; [E, E+N) are self loops (src=dst=id-E).
__global__ __launch_bounds__(256) void k_edge(const int* __restrict__ ei, int E, int N) {
    int e = blockIdx.x * blockDim.x + threadIdx.x;
    if (e >= E + N) return;
    int src, dst;
    if (e < E) { src = ei[e]; dst = ei[E + e]; }
    else       { src = dst = e - E; }
    float v = g_as[src] + g_ad[dst];
    v = (v > 0.0f) ? v : NEG_SLOPE * v;
    float ex = __expf(v);   // no max-shift: exp(e)/sum identical, |e| small
    g_ex[e] = ex;
    atomicAdd(&g_s[dst], ex);
}

// ---------------- K3: weighted scatter-add, 16 threads per edge ----------------
__global__ __launch_bounds__(256) void k_scatter(const int* __restrict__ ei,
                                                 float* __restrict__ out, int E, int N) {
    int t = blockIdx.x * blockDim.x + threadIdx.x;
    int e = t >> 4;
    if (e >= E + N) return;
    int c = (t & 15) << 2;   // float4 chunk within the 64-dim row
    int src, dst;
    if (e < E) { src = ei[e]; dst = ei[E + e]; }
    else       { src = dst = e - E; }
    float alpha = __fdividef(g_ex[e], g_s[dst]);
    float4 hv = *(const float4*)(g_h + (size_t)src * OUT_DIM + c);
    float4 m = make_float4(hv.x * alpha, hv.y * alpha, hv.z * alpha, hv.w * alpha);
    float* p = out + (size_t)dst * OUT_DIM + c;
    asm volatile("red.global.add.v4.f32 [%0], {%1, %2, %3, %4};"
                 :: "l"(p), "f"(m.x), "f"(m.y), "f"(m.z), "f"(m.w)
                 : "memory");
}

// ---------------- launcher ----------------
extern "C" void kernel_launch(void* const* d_in, const int* in_sizes, int n_in,
                              void* d_out, int out_size) {
    const float* x     = (const float*)d_in[0];
    const int*   ei    = (const int*)  d_in[1];
    const float* W     = (const float*)d_in[2];
    const float* a_src = (const float*)d_in[3];
    const float* a_dst = (const float*)d_in[4];
    const float* bias  = (const float*)d_in[5];
    float* out = (float*)d_out;

    int N = in_sizes[0] / IN_DIM;
    int E = in_sizes[1] / 2;

    static bool attr_done = false;
    if (!attr_done) {
        cudaFuncSetAttribute(k_gemm, cudaFuncAttributeMaxDynamicSharedMemorySize, GEMM_SMEM);
        attr_done = true;
    }

    k_init<<<(N * OUT_DIM + 255) / 256, 256>>>(out, bias, N);
    k_gemm<<<(N + TR - 1) / TR, 256, GEMM_SMEM>>>(x, W, N);
    k_alpha<<<(N * 32 + 255) / 256, 256>>>(a_src, a_dst, N);
    int T = E + N;
    k_edge<<<(T + 255) / 256, 256>>>(ei, E, N);
    long long tot = (long long)T * 16;
    k_scatter<<<(int)((tot + 255) / 256), 256>>>(ei, out, E, N);
}

// round 2
// speedup vs baseline: 1.1834x; 1.1834x over previous
#include <cuda_runtime.h>
#include <cuda_bf16.h>

// GATConv heads=1, self loops. h = x@W; out[d] = bias + sum_e softmax_d(lrelu(as[s]+ad[d])) h[s]
// Round 2: CSR-by-dst build + warp-per-node aggregation (no output atomics).

#define IN_DIM   128
#define OUT_DIM  64
#define N_MAX    100000
#define E_MAX    1600000
#define NEG_SLOPE 0.2f
#define SCAN_BLK 1024

// ---------------- device scratch ----------------
__device__ __align__(16) float g_h[(size_t)N_MAX * OUT_DIM];   // 25.6 MB
__device__ float g_as[N_MAX];
__device__ float g_ad[N_MAX];
__device__ float g_ex[E_MAX + N_MAX];        // per-edge exp, CSR order
__device__ int   g_cnt[N_MAX];               // degree+1
__device__ int   g_off[N_MAX];               // block-local exclusive scan
__device__ int   g_start[N_MAX];             // global CSR row start
__device__ int   g_cur[N_MAX];               // fill cursor
__device__ int   g_bsum[256];
__device__ int   g_bbase[256];
__device__ int   g_srcbuf[E_MAX + N_MAX];    // CSR: src per slot

// ---------------- K0: counters = 1 (self loop pre-counted) ----------------
__global__ void k_init(int N) {
    int i = blockIdx.x * blockDim.x + threadIdx.x;
    if (i < N) g_cnt[i] = 1;
}

// ---------------- K0b: histogram of dst ----------------
__global__ __launch_bounds__(256) void k_hist(const int* __restrict__ ei, int E) {
    int e = blockIdx.x * blockDim.x + threadIdx.x;
    if (e < E) atomicAdd(&g_cnt[ei[E + e]], 1);
}

// ---------------- scan: block-level ----------------
__global__ __launch_bounds__(SCAN_BLK) void k_scan_a(int N) {
    __shared__ int wsum[32];
    int i = blockIdx.x * SCAN_BLK + threadIdx.x;
    int lane = threadIdx.x & 31, w = threadIdx.x >> 5;
    int v = (i < N) ? g_cnt[i] : 0;
    int s = v;
#pragma unroll
    for (int o = 1; o < 32; o <<= 1) { int t = __shfl_up_sync(~0u, s, o); if (lane >= o) s += t; }
    if (lane == 31) wsum[w] = s;
    __syncthreads();
    if (w == 0) {
        int t = wsum[lane];
#pragma unroll
        for (int o = 1; o < 32; o <<= 1) { int u = __shfl_up_sync(~0u, t, o); if (lane >= o) t += u; }
        wsum[lane] = t;
    }
    __syncthreads();
    int excl = s - v + (w > 0 ? wsum[w - 1] : 0);
    if (i < N) g_off[i] = excl;
    if (threadIdx.x == SCAN_BLK - 1) g_bsum[blockIdx.x] = wsum[31];
}

__global__ void k_scan_b(int NB) {   // 1 block, 128 threads
    __shared__ int wsum[4];
    int t = threadIdx.x, lane = t & 31, w = t >> 5;
    int v = (t < NB) ? g_bsum[t] : 0;
    int s = v;
#pragma unroll
    for (int o = 1; o < 32; o <<= 1) { int u = __shfl_up_sync(~0u, s, o); if (lane >= o) s += u; }
    if (lane == 31) wsum[w] = s;
    __syncthreads();
    int base = 0;
    for (int j = 0; j < w; j++) base += wsum[j];
    if (t < NB) g_bbase[t] = base + s - v;
}

__global__ void k_scan_c(int N) {
    int i = blockIdx.x * blockDim.x + threadIdx.x;
    if (i < N) {
        int s = g_off[i] + g_bbase[i >> 10];
        g_start[i] = s;
        g_cur[i] = s;
    }
}

// ---------------- fill CSR buckets (edges + self loops) ----------------
__global__ __launch_bounds__(256) void k_fill(const int* __restrict__ ei, int E, int N) {
    int e = blockIdx.x * blockDim.x + threadIdx.x;
    if (e >= E + N) return;
    int src, dst;
    if (e < E) { src = ei[e]; dst = ei[E + e]; }
    else       { src = dst = e - E; }
    int pos = atomicAdd(&g_cur[dst], 1);
    g_srcbuf[pos] = src;
}

// ---------------- K1: h = x @ W  (fp32, f32x2-packed FMA) ----------------
#define TR 64
#define GEMM_SMEM (IN_DIM * OUT_DIM * 4 + TR * 129 * 4)

__global__ __launch_bounds__(256) void k_gemm(const float* __restrict__ x,
                                              const float* __restrict__ W, int N) {
    extern __shared__ float smem[];
    float* Ws = smem;
    float* Xs = smem + IN_DIM * OUT_DIM;

    int tid = threadIdx.x;
    int rowBase = blockIdx.x * TR;

    for (int i = tid; i < (IN_DIM * OUT_DIM) / 4; i += 256)
        ((float4*)Ws)[i] = ((const float4*)W)[i];

    for (int i = tid; i < (TR * IN_DIM) / 4; i += 256) {
        int r  = i >> 5;
        int kq = i & 31;
        int row = rowBase + r;
        float4 v = (row < N) ? ((const float4*)x)[(size_t)row * 32 + kq]
                             : make_float4(0.f, 0.f, 0.f, 0.f);
        float* p = &Xs[r * 129 + kq * 4];
        p[0] = v.x; p[1] = v.y; p[2] = v.z; p[3] = v.w;
    }
    __syncthreads();

    int w    = tid >> 5;
    int lane = tid & 31;
    int rl   = ((w & 1) << 5) + lane;
    int cb   = (w >> 1) << 4;

    unsigned long long acc[8];
#pragma unroll
    for (int j = 0; j < 8; j++) acc[j] = 0ULL;

    const ulonglong2* Ws2 = (const ulonglong2*)Ws;

#pragma unroll 8
    for (int k = 0; k < IN_DIM; k++) {
        float xv = Xs[rl * 129 + k];
        unsigned long long xp;
        asm("mov.b64 %0, {%1, %1};" : "=l"(xp) : "f"(xv));
        int base = k * 16 + (cb >> 2);
#pragma unroll
        for (int j = 0; j < 4; j++) {
            ulonglong2 ww = Ws2[base + j];
            asm("fma.rn.f32x2 %0, %1, %2, %0;" : "+l"(acc[2 * j])     : "l"(xp), "l"(ww.x));
            asm("fma.rn.f32x2 %0, %1, %2, %0;" : "+l"(acc[2 * j + 1]) : "l"(xp), "l"(ww.y));
        }
    }

    int row = rowBase + rl;
    if (row < N) {
        float tmp[16];
#pragma unroll
        for (int j = 0; j < 8; j++) {
            float lo, hi;
            asm("mov.b64 {%0, %1}, %2;" : "=f"(lo), "=f"(hi) : "l"(acc[j]));
            tmp[2 * j] = lo; tmp[2 * j + 1] = hi;
        }
        float4* hp = (float4*)(g_h + (size_t)row * OUT_DIM + cb);
#pragma unroll
        for (int j = 0; j < 4; j++)
            hp[j] = make_float4(tmp[4 * j], tmp[4 * j + 1], tmp[4 * j + 2], tmp[4 * j + 3]);
    }
}

// ---------------- K1b: per-node attention logits ----------------
__global__ __launch_bounds__(256) void k_alpha(const float* __restrict__ a_src,
                                               const float* __restrict__ a_dst, int N) {
    int gwarp = (blockIdx.x * blockDim.x + threadIdx.x) >> 5;
    int lane  = threadIdx.x & 31;
    if (gwarp >= N) return;
    const float* hr = g_h + (size_t)gwarp * OUT_DIM;
    float v0 = hr[lane], v1 = hr[lane + 32];
    float ps = v0 * a_src[lane] + v1 * a_src[lane + 32];
    float pd = v0 * a_dst[lane] + v1 * a_dst[lane + 32];
#pragma unroll
    for (int o = 16; o; o >>= 1) {
        ps += __shfl_down_sync(0xFFFFFFFFu, ps, o);
        pd += __shfl_down_sync(0xFFFFFFFFu, pd, o);
    }
    if (lane == 0) { g_as[gwarp] = ps; g_ad[gwarp] = pd; }
}

// ---------------- K3: warp-per-dst aggregation (no atomics) ----------------
__global__ __launch_bounds__(256) void k_gat(const float* __restrict__ bias,
                                             float* __restrict__ out, int N) {
    int gw   = (blockIdx.x * blockDim.x + threadIdx.x) >> 5;
    int lane = threadIdx.x & 31;
    if (gw >= N) return;
    int start = g_start[gw];
    int cnt   = g_cnt[gw];
    float ad  = g_ad[gw];

    // phase 1: Sigma exp over edges, lane-parallel, coalesced CSR reads
    float psum = 0.0f;
    for (int base = 0; base < cnt; base += 32) {
        int i = base + lane;
        float ex = 0.0f;
        if (i < cnt) {
            int src = g_srcbuf[start + i];
            float v = g_as[src] + ad;
            v = (v > 0.0f) ? v : NEG_SLOPE * v;
            ex = __expf(v);
            g_ex[start + i] = ex;
        }
        psum += ex;
    }
#pragma unroll
    for (int o = 16; o; o >>= 1) psum += __shfl_xor_sync(~0u, psum, o);
    float invS = __fdividef(1.0f, psum);

    // phase 2: serial edge loop, uniform (broadcast) src/ex loads, warp-wide h gather
    float2 acc = make_float2(0.0f, 0.0f);
    const float2* hb = (const float2*)g_h;
#pragma unroll 4
    for (int e = 0; e < cnt; e++) {
        int   src = g_srcbuf[start + e];
        float al  = g_ex[start + e] * invS;
        float2 hv = hb[(size_t)src * 32 + lane];
        acc.x += al * hv.x;
        acc.y += al * hv.y;
    }
    float2 bv = ((const float2*)bias)[lane];
    acc.x += bv.x; acc.y += bv.y;
    ((float2*)out)[(size_t)gw * 32 + lane] = acc;
}

// ---------------- launcher ----------------
extern "C" void kernel_launch(void* const* d_in, const int* in_sizes, int n_in,
                              void* d_out, int out_size) {
    const float* x     = (const float*)d_in[0];
    const int*   ei    = (const int*)  d_in[1];
    const float* W     = (const float*)d_in[2];
    const float* a_src = (const float*)d_in[3];
    const float* a_dst = (const float*)d_in[4];
    const float* bias  = (const float*)d_in[5];
    float* out = (float*)d_out;

    int N = in_sizes[0] / IN_DIM;
    int E = in_sizes[1] / 2;
    int T = E + N;
    int NB = (N + SCAN_BLK - 1) / SCAN_BLK;

    static bool attr_done = false;
    if (!attr_done) {
        cudaFuncSetAttribute(k_gemm, cudaFuncAttributeMaxDynamicSharedMemorySize, GEMM_SMEM);
        attr_done = true;
    }

    // CSR build
    k_init<<<(N + 255) / 256, 256>>>(N);
    k_hist<<<(E + 255) / 256, 256>>>(ei, E);
    k_scan_a<<<NB, SCAN_BLK>>>(N);
    k_scan_b<<<1, 128>>>(NB);
    k_scan_c<<<(N + 255) / 256, 256>>>(N);
    k_fill<<<(T + 255) / 256, 256>>>(ei, E, N);

    // features + logits
    k_gemm<<<(N + TR - 1) / TR, 256, GEMM_SMEM>>>(x, W, N);
    k_alpha<<<(N * 32 + 255) / 256, 256>>>(a_src, a_dst, N);

    // aggregation
    k_gat<<<(N * 32 + 255) / 256, 256>>>(bias, out, N);
}